// round 9
// baseline (speedup 1.0000x reference)
#include <cuda_runtime.h>
#include <cuda_bf16.h>

// out[b,p,h] = sum_{i,j} premise[b,p,i] * kernel[p,h,i,j] * hypothesis[b,h,j]
// B=8, P=96, H=96, D1=D2=128
//
// HBM-bound (604 MB K streamed once). Persistent scheme: 912 CTAs (152 SM x 6),
// each owns a contiguous chunk of ~10 (p,h) tiles (h-major within p), so
// premise staging happens ~once per chunk and there are no wave transitions.
// Mainloop: thread (w,l) owns columns 4l..4l+3 (LDG.128, evict-first) and rows
// i = w mod 4; batch pairs via packed fma.rn.f32x2.

#define NB 8
#define NP 96
#define NH 96
#define ND 128
#define NTILES (NP * NH)
#define NCTA 912

using u64 = unsigned long long;

__device__ __forceinline__ u64 pack2(float lo, float hi) {
    u64 r;
    asm("mov.b64 %0, {%1, %2};" : "=l"(r) : "f"(lo), "f"(hi));
    return r;
}
__device__ __forceinline__ u64 fma2(u64 a, u64 b, u64 c) {
    u64 d;
    asm("fma.rn.f32x2 %0, %1, %2, %3;" : "=l"(d) : "l"(a), "l"(b), "l"(c));
    return d;
}
__device__ __forceinline__ void unpack2(u64 v, float& lo, float& hi) {
    asm("mov.b64 {%0, %1}, %2;" : "=f"(lo), "=f"(hi) : "l"(v));
}

__global__ void __launch_bounds__(128, 6)
interaction_kernel(const float* __restrict__ premise,
                   const float* __restrict__ hyp,
                   const float* __restrict__ kern,
                   float* __restrict__ out)
{
    const int tid = threadIdx.x;     // 0..127
    const int w   = tid >> 5;        // warp: rows i ≡ w (mod 4)
    const int l   = tid & 31;        // lane: columns 4l..4l+3

    __shared__ __align__(16) float pre_s[ND * NB];  // [i][b]
    __shared__ float red[4][NB];

    // Contiguous balanced chunk of tiles for this CTA
    const int cta  = blockIdx.x;
    const int nCTA = gridDim.x;
    const int t0 = (int)(((long long)cta       * NTILES) / nCTA);
    const int t1 = (int)(((long long)(cta + 1) * NTILES) / nCTA);

    const ulonglong2* pre2 = reinterpret_cast<const ulonglong2*>(pre_s);

    int p_cached = -1;
    for (int t = t0; t < t1; t++) {
        const int p = t / NH;
        const int h = t - p * NH;

        if (p != p_cached) {
            __syncthreads();   // prior tile's pre_s readers are done
#pragma unroll
            for (int r = 0; r < 8; r++) {
                int idx = tid + r * 128;
                int i = idx >> 3;
                int b = idx & 7;
                pre_s[idx] = premise[((size_t)b * NP + p) * ND + i];
            }
            __syncthreads();
            p_cached = p;
        }

        // K tile: kernel[p,h,i,j]; this thread reads float4 at (i, 4l)
        const float4* kp = reinterpret_cast<const float4*>(
            kern + (((size_t)(p * NH + h)) << 14)) + l;

        u64 acc[4][4];
#pragma unroll
        for (int bp = 0; bp < 4; bp++)
#pragma unroll
            for (int jj = 0; jj < 4; jj++) acc[bp][jj] = 0ull;

#pragma unroll 4
        for (int ii = 0; ii < 32; ii++) {
            const int i = w + 4 * ii;
            float4 kv = __ldcs(&kp[i * 32]);     // streaming LDG.128
            ulonglong2 pa = pre2[i * 2 + 0];     // pre[i][0..3] as 2x f32x2
            ulonglong2 pb = pre2[i * 2 + 1];     // pre[i][4..7]
            u64 pr[4] = { pa.x, pa.y, pb.x, pb.y };
            u64 k2[4] = { pack2(kv.x, kv.x), pack2(kv.y, kv.y),
                          pack2(kv.z, kv.z), pack2(kv.w, kv.w) };
#pragma unroll
            for (int bp = 0; bp < 4; bp++)
#pragma unroll
                for (int jj = 0; jj < 4; jj++)
                    acc[bp][jj] = fma2(k2[jj], pr[bp], acc[bp][jj]);
        }

        // Epilogue: fold hypothesis[b, h, 4l..4l+3], reduce over columns
        float s[NB];
#pragma unroll
        for (int bp = 0; bp < 4; bp++) {
            float4 h0 = *reinterpret_cast<const float4*>(
                &hyp[((size_t)(2 * bp + 0) * NH + h) * ND + 4 * l]);
            float4 h1 = *reinterpret_cast<const float4*>(
                &hyp[((size_t)(2 * bp + 1) * NH + h) * ND + 4 * l]);
            u64 hs0 = pack2(h0.x, h1.x);
            u64 hs1 = pack2(h0.y, h1.y);
            u64 hs2 = pack2(h0.z, h1.z);
            u64 hs3 = pack2(h0.w, h1.w);
            u64 v = fma2(acc[bp][0], hs0, 0ull);
            v = fma2(acc[bp][1], hs1, v);
            v = fma2(acc[bp][2], hs2, v);
            v = fma2(acc[bp][3], hs3, v);
            unpack2(v, s[2 * bp], s[2 * bp + 1]);
        }

#pragma unroll
        for (int off = 16; off; off >>= 1) {
#pragma unroll
            for (int b = 0; b < NB; b++)
                s[b] += __shfl_down_sync(0xffffffffu, s[b], off);
        }

        if (l == 0) {
#pragma unroll
            for (int b = 0; b < NB; b++) red[w][b] = s[b];
        }
        __syncthreads();

        if (tid < NB) {
            float v = red[0][tid] + red[1][tid] + red[2][tid] + red[3][tid];
            out[((size_t)tid * NP + p) * NH + h] = v;
        }
        __syncthreads();   // protect red[] and pre_s reuse on next tile
    }
}

extern "C" void kernel_launch(void* const* d_in, const int* in_sizes, int n_in,
                              void* d_out, int out_size) {
    const float* premise = (const float*)d_in[0];  // (8, 96, 128)
    const float* hyp     = (const float*)d_in[1];  // (8, 96, 128)
    const float* kern    = (const float*)d_in[2];  // (96, 96, 128, 128)
    float* out = (float*)d_out;                    // (8, 96, 96)

    interaction_kernel<<<NCTA, 128>>>(premise, hyp, kern, out);
}

// round 10
// speedup vs baseline: 1.0597x; 1.0597x over previous
#include <cuda_runtime.h>
#include <cuda_bf16.h>

// out[b,p,h] = sum_{i,j} premise[b,p,i] * kernel[p,h,i,j] * hypothesis[b,h,j]
// B=8, P=96, H=96, D1=D2=128
//
// HBM-bound (604 MB K streamed once). One CTA per (p,h) (R8 scheme; the
// persistent variant regressed). Thread (w,l) owns columns 4l..4l+3 via
// LDG.128 read as ulonglong2 = two native f32x2 pairs (k0,k1),(k2,k3).
// Premise is staged DUPLICATED in smem ((pre,pre) per u64) so the mainloop
// has zero pack instructions: per K row per thread just
//   1 LDG.128 + 4 broadcast LDS.128 + 16 fma.rn.f32x2.
// Unroll 8 for ~8 LDG.128 in flight per warp.

#define NB 8
#define NP 96
#define NH 96
#define ND 128

using u64 = unsigned long long;

__device__ __forceinline__ u64 fma2(u64 a, u64 b, u64 c) {
    u64 d;
    asm("fma.rn.f32x2 %0, %1, %2, %3;" : "=l"(d) : "l"(a), "l"(b), "l"(c));
    return d;
}
__device__ __forceinline__ u64 dup2(float v) {
    u64 r;
    asm("mov.b64 %0, {%1, %1};" : "=l"(r) : "f"(v));
    return r;
}
__device__ __forceinline__ void unpack2(u64 v, float& lo, float& hi) {
    asm("mov.b64 {%0, %1}, %2;" : "=f"(lo), "=f"(hi) : "l"(v));
}

__global__ void __launch_bounds__(128, 6)
interaction_kernel(const float* __restrict__ premise,
                   const float* __restrict__ hyp,
                   const float* __restrict__ kern,
                   float* __restrict__ out)
{
    const int h   = blockIdx.x;      // 0..95
    const int p   = blockIdx.y;      // 0..95
    const int tid = threadIdx.x;     // 0..127
    const int w   = tid >> 5;        // warp: rows i ≡ w (mod 4)
    const int l   = tid & 31;        // lane: columns 4l..4l+3

    __shared__ __align__(16) u64 pre_d[ND * NB];  // [i][b], (pre,pre) dup, 8 KB
    __shared__ float red[4][NB];

    // Stage premise[:, p, :] duplicated: pre_d[i*8 + b] = (v, v)
#pragma unroll
    for (int r = 0; r < 8; r++) {
        int idx = tid + r * 128;          // 0..1023
        int i = idx >> 3;
        int b = idx & 7;
        pre_d[idx] = dup2(premise[((size_t)b * NP + p) * ND + i]);
    }
    __syncthreads();

    // K tile: kernel[p,h,i,j]; this thread reads 16B at (i, 4l)
    const ulonglong2* kp = reinterpret_cast<const ulonglong2*>(
        kern + (((size_t)(p * NH + h)) << 14)) + l;   // row i -> kp[i*32]

    const ulonglong2* pre2 = reinterpret_cast<const ulonglong2*>(pre_d);

    // acc[b][jp]: f32x2 accumulator for columns (4l+2jp, 4l+2jp+1), batch b
    u64 acc[NB][2];
#pragma unroll
    for (int b = 0; b < NB; b++) { acc[b][0] = 0ull; acc[b][1] = 0ull; }

#pragma unroll 8
    for (int ii = 0; ii < 32; ii++) {
        const int i = w + 4 * ii;
        ulonglong2 kv = kp[i * 32];          // (k0,k1),(k2,k3) — native pairs
        ulonglong2 pr01 = pre2[i * 4 + 0];   // dup pre[i][0], pre[i][1]
        ulonglong2 pr23 = pre2[i * 4 + 1];
        ulonglong2 pr45 = pre2[i * 4 + 2];
        ulonglong2 pr67 = pre2[i * 4 + 3];
        u64 pr[NB] = { pr01.x, pr01.y, pr23.x, pr23.y,
                       pr45.x, pr45.y, pr67.x, pr67.y };
#pragma unroll
        for (int b = 0; b < NB; b++) {
            acc[b][0] = fma2(kv.x, pr[b], acc[b][0]);
            acc[b][1] = fma2(kv.y, pr[b], acc[b][1]);
        }
    }

    // Epilogue: fold hypothesis[b, h, 4l..4l+3] (float4 = two f32x2 pairs)
    float s[NB];
#pragma unroll
    for (int b = 0; b < NB; b++) {
        ulonglong2 hv = *reinterpret_cast<const ulonglong2*>(
            &hyp[((size_t)b * NH + h) * ND + 4 * l]);
        u64 t = fma2(acc[b][0], hv.x, 0ull);
        t = fma2(acc[b][1], hv.y, t);
        float lo, hi;
        unpack2(t, lo, hi);
        s[b] = lo + hi;
    }

    // Reduce over 32 lanes (j dimension)
#pragma unroll
    for (int off = 16; off; off >>= 1) {
#pragma unroll
        for (int b = 0; b < NB; b++)
            s[b] += __shfl_down_sync(0xffffffffu, s[b], off);
    }

    if (l == 0) {
#pragma unroll
        for (int b = 0; b < NB; b++) red[w][b] = s[b];
    }
    __syncthreads();

    if (tid < NB) {
        float v = red[0][tid] + red[1][tid] + red[2][tid] + red[3][tid];
        out[((size_t)tid * NP + p) * NH + h] = v;
    }
}

extern "C" void kernel_launch(void* const* d_in, const int* in_sizes, int n_in,
                              void* d_out, int out_size) {
    const float* premise = (const float*)d_in[0];  // (8, 96, 128)
    const float* hyp     = (const float*)d_in[1];  // (8, 96, 128)
    const float* kern    = (const float*)d_in[2];  // (96, 96, 128, 128)
    float* out = (float*)d_out;                    // (8, 96, 96)

    dim3 grid(NH, NP);
    interaction_kernel<<<grid, 128>>>(premise, hyp, kern, out);
}